// round 1
// baseline (speedup 1.0000x reference)
#include <cuda_runtime.h>

// BilateralSliceApply on GB300.
// Shapes fixed by the problem instance:
//   grid : (B=4, gh=16, gw=16, gd=8, nc=12)  float32
//   guide: (B, 1024, 1024)                    float32
//   inp  : (B, 1024, 1024, 3)                 float32
//   out  : (B, 1024, 1024, 3)                 float32
//
// Tap rule (matches jax reference _axis_taps):
//   g = (coord + 0.5) * (gsize / size)   (x,y)   or  guide * gd   (z)
//   f = floor(g - 0.5); taps at f, f+1; w(f) = 1-t, w(f+1) = t where t = g-0.5-f
//   weight uses UNCLAMPED index, value uses CLAMPED index.
//
// Strategy: block = 64x4 pixel tile. Grid footprint for a tile is <= 3 y-cells
// x 3 x-cells x 8 z x 12 c = 864 floats (3.4 KB) -> staged in shared as float4.
// All 8 taps per pixel read from shared (conflict-free: z-stride = 12 words ->
// distinct 4-aligned bank ranges mod 32; same-z lanes broadcast).

#define GH 16
#define GW 16
#define GD 8
#define NC 12
#define HH 1024
#define WW 1024
#define TILE_X 64
#define TILE_Y 4

__global__ void __launch_bounds__(256) bsa_kernel(
    const float* __restrict__ grid,
    const float* __restrict__ guide,
    const float* __restrict__ inp,
    float* __restrict__ out)
{
    // [yi(3)][xi(3)][z(8)][c4(3)] float4
    __shared__ float4 sg[3 * 3 * GD * 3];

    const int bx = blockIdx.x;   // x tile, 0..15
    const int by = blockIdx.y;   // y tile, 0..255
    const int b  = blockIdx.z;   // batch, 0..3
    const int tx = threadIdx.x;  // 0..63
    const int ty = threadIdx.y;  // 0..3
    const int tid = ty * TILE_X + tx;

    const float inv64 = 1.0f / 64.0f;  // gw/W = gh/H = 16/1024

    // Tile-wide minimum unclamped tap index along x and y.
    // x: gx(min) = (bx*64 + 0.5)/64 = bx + 1/128  -> floor(gx-0.5) = bx-1 always.
    const int xbase = bx - 1;
    const int ybase = (int)floorf(((float)(by * TILE_Y) + 0.5f) * inv64 - 0.5f);

    // Cooperative load of the grid footprint: 216 float4 (one per thread tid<216).
    if (tid < 216) {
        int c4 = tid % 3;
        int r  = tid / 3;
        int z  = r % GD; r /= GD;
        int xi = r % 3;
        int yi = r / 3;
        int gy = min(max(ybase + yi, 0), GH - 1);
        int gx = min(max(xbase + xi, 0), GW - 1);
        const float4* gp = reinterpret_cast<const float4*>(
            grid + (size_t)(((b * GH + gy) * GW + gx) * GD + z) * NC);
        sg[tid] = gp[c4];
    }
    __syncthreads();

    const int x = bx * TILE_X + tx;
    const int y = by * TILE_Y + ty;

    // x/y tap weights
    const float gxf = ((float)x + 0.5f) * inv64;
    const float gyf = ((float)y + 0.5f) * inv64;
    float txf = gxf - 0.5f; float fx = floorf(txf); float wx1 = txf - fx;
    float tyf = gyf - 0.5f; float fy = floorf(tyf); float wy1 = tyf - fy;
    const int sx = (int)fx - xbase;  // 0 or 1
    const int sy = (int)fy - ybase;  // 0 or 1

    // z taps from guide
    const size_t pix = (size_t)(b * HH + y) * WW + x;
    const float g  = __ldg(guide + pix);
    const float gz = g * (float)GD;
    float tzf = gz - 0.5f; float fz = floorf(tzf); float wz1 = tzf - fz;
    const float wz0 = 1.0f - wz1;
    const int iz = (int)fz;
    const int z0 = min(max(iz, 0), GD - 1);
    const int z1 = min(max(iz + 1, 0), GD - 1);

    float acc[12];
    #pragma unroll
    for (int i = 0; i < 12; i++) acc[i] = 0.0f;

    #pragma unroll
    for (int dy = 0; dy < 2; dy++) {
        const float wy = dy ? wy1 : (1.0f - wy1);
        const int ys = sy + dy;
        #pragma unroll
        for (int dx = 0; dx < 2; dx++) {
            const float wxy = wy * (dx ? wx1 : (1.0f - wx1));
            const int xs = sx + dx;
            const int cell = (ys * 3 + xs) * GD;
            const int s0 = (cell + z0) * 3;
            const int s1 = (cell + z1) * 3;
            const float w0 = wxy * wz0;
            const float w1 = wxy * wz1;
            #pragma unroll
            for (int c4 = 0; c4 < 3; c4++) {
                const float4 a  = sg[s0 + c4];
                const float4 bb = sg[s1 + c4];
                acc[c4 * 4 + 0] += w0 * a.x + w1 * bb.x;
                acc[c4 * 4 + 1] += w0 * a.y + w1 * bb.y;
                acc[c4 * 4 + 2] += w0 * a.z + w1 * bb.z;
                acc[c4 * 4 + 3] += w0 * a.w + w1 * bb.w;
            }
        }
    }

    // Apply: out[o] = sum_c coeff[o,c]*in[c] + coeff[o,3]
    const float* ip = inp + pix * 3;
    const float i0 = __ldg(ip + 0);
    const float i1 = __ldg(ip + 1);
    const float i2 = __ldg(ip + 2);
    float* op = out + pix * 3;
    op[0] = acc[0] * i0 + acc[1] * i1 + acc[2]  * i2 + acc[3];
    op[1] = acc[4] * i0 + acc[5] * i1 + acc[6]  * i2 + acc[7];
    op[2] = acc[8] * i0 + acc[9] * i1 + acc[10] * i2 + acc[11];
}

extern "C" void kernel_launch(void* const* d_in, const int* in_sizes, int n_in,
                              void* d_out, int out_size)
{
    const float* grid  = (const float*)d_in[0];
    const float* guide = (const float*)d_in[1];
    const float* inp   = (const float*)d_in[2];
    float* out = (float*)d_out;

    const int B = in_sizes[1] / (HH * WW);  // 4

    dim3 blk(TILE_X, TILE_Y, 1);                       // 256 threads
    dim3 grd(WW / TILE_X, HH / TILE_Y, B);             // (16, 256, 4)
    bsa_kernel<<<grd, blk>>>(grid, guide, inp, out);
}

// round 2
// speedup vs baseline: 1.5864x; 1.5864x over previous
#include <cuda_runtime.h>

// BilateralSliceApply on GB300 — Round 2.
// grid (4,16,16,8,12) f32, guide (4,1024,1024), inp/out (4,1024,1024,3).
//
// Structure: one block = one image row of 512 pixels (512 threads).
// The y-taps (indices AND weights) are uniform over a row, so y-interp is
// hoisted: stage PY[xi(10)][z(8)][c(12)] = wy0*grid[cy0] + wy1*grid[cy1]
// cooperatively (240 threads, 2 coalesced LDG.128 + 1 STS.128 each).
// Main loop per pixel: 4 taps (2x * 2z) * 48B = 192 B of conflict-free
// shared reads (z-stride = 12 words -> distinct 4-aligned bank groups),
// accumulated with packed fma.rn.f32x2 (FFMA2).

#define GH 16
#define GW 16
#define GD 8
#define NC 12
#define HH 1024
#define WW 1024
#define TPB 512              // one row-block of 512 pixels
#define NXS 10               // x tap slots covered by a 512-px row

typedef unsigned long long ull;

__device__ __forceinline__ ull pk2(float lo, float hi) {
    ull r; asm("mov.b64 %0, {%1, %2};" : "=l"(r) : "f"(lo), "f"(hi)); return r;
}
__device__ __forceinline__ float2 upk2(ull v) {
    float2 r; asm("mov.b64 {%0, %1}, %2;" : "=f"(r.x), "=f"(r.y) : "l"(v)); return r;
}
__device__ __forceinline__ ull f2fma(ull a, ull b, ull c) {
    ull d; asm("fma.rn.f32x2 %0, %1, %2, %3;" : "=l"(d) : "l"(a), "l"(b), "l"(c)); return d;
}

__global__ void __launch_bounds__(TPB) bsa_kernel(
    const float* __restrict__ grid,
    const float* __restrict__ guide,
    const float* __restrict__ inp,
    float* __restrict__ out)
{
    // PY[xi][z][c]: 10*8*12 floats = 3.75 KB, stored as float4 triplets.
    __shared__ float4 PY[NXS * GD * 3];

    const int bx  = blockIdx.x;          // 0..1 (x half of the row)
    const int y   = blockIdx.y;          // 0..1023
    const int b   = blockIdx.z;          // 0..3
    const int tid = threadIdx.x;         // 0..511
    const int x   = bx * TPB + tid;

    // ---- per-pixel loads issued early (overlap with stage) ----
    const size_t pix = (size_t)(b * HH + y) * WW + x;
    const float gdv = __ldg(guide + pix);
    const float i0 = __ldg(inp + pix * 3 + 0);
    const float i1 = __ldg(inp + pix * 3 + 1);
    const float i2 = __ldg(inp + pix * 3 + 2);

    // ---- y taps: uniform over the row. Exact integer form:
    // gy - 0.5 = ((y+0.5)/64) - 0.5 = (2y-63)/128
    const int vy = 2 * y - 63;
    const int fy = vy >> 7;                       // floor, unclamped
    const float wy1 = (float)(vy & 127) * (1.0f / 128.0f);
    const float wy0 = 1.0f - wy1;
    const int cy0 = min(max(fy,     0), GH - 1);
    const int cy1 = min(max(fy + 1, 0), GH - 1);

    const int xbase = bx * (TPB / 64) - 1;        // min unclamped x tap

    // ---- stage: PY[xi][z][c4] = wy0*grid[cy0,...] + wy1*grid[cy1,...] ----
    if (tid < NXS * GD * 3) {
        const int c4 = tid % 3;
        const int z  = (tid / 3) & (GD - 1);
        const int xi = tid / (3 * GD);
        const int gx = min(max(xbase + xi, 0), GW - 1);
        const float4* g0 = reinterpret_cast<const float4*>(grid)
            + (size_t)(((b * GH + cy0) * GW + gx) * GD + z) * 3 + c4;
        const float4* g1 = reinterpret_cast<const float4*>(grid)
            + (size_t)(((b * GH + cy1) * GW + gx) * GD + z) * 3 + c4;
        const float4 a = __ldg(g0);
        const float4 bb = __ldg(g1);
        float4 r;
        r.x = wy0 * a.x + wy1 * bb.x;
        r.y = wy0 * a.y + wy1 * bb.y;
        r.z = wy0 * a.z + wy1 * bb.z;
        r.w = wy0 * a.w + wy1 * bb.w;
        PY[tid] = r;
    }
    __syncthreads();

    // ---- x taps (exact integer form) ----
    const int vx = 2 * x - 63;
    const int fx = vx >> 7;                       // unclamped
    const float wx1 = (float)(vx & 127) * (1.0f / 128.0f);
    const float wx0 = 1.0f - wx1;
    const int sx = fx - xbase;                    // 0..8

    // ---- z taps from guide ----
    const float gz = gdv * (float)GD;
    const float tz = gz - 0.5f;
    const float fz = floorf(tz);
    const float wz1 = tz - fz;
    const float wz0 = 1.0f - wz1;
    const int iz = (int)fz;
    const int z0 = min(max(iz,     0), GD - 1);
    const int z1 = min(max(iz + 1, 0), GD - 1);

    // packed tap weights
    const ull w00 = pk2(wx0 * wz0, wx0 * wz0);
    const ull w01 = pk2(wx0 * wz1, wx0 * wz1);
    const ull w10 = pk2(wx1 * wz0, wx1 * wz0);
    const ull w11 = pk2(wx1 * wz1, wx1 * wz1);

    const ulonglong2* PY2 = reinterpret_cast<const ulonglong2*>(PY);
    const int e00 = (sx * GD + z0) * 3;
    const int e01 = (sx * GD + z1) * 3;
    const int e10 = e00 + GD * 3;
    const int e11 = e01 + GD * 3;

    ull a0 = pk2(0.f, 0.f), a1 = a0, a2 = a0, a3 = a0, a4 = a0, a5 = a0;

    {   // tap (x0, z0)
        ulonglong2 p0 = PY2[e00], p1 = PY2[e00 + 1], p2 = PY2[e00 + 2];
        a0 = f2fma(p0.x, w00, a0); a1 = f2fma(p0.y, w00, a1);
        a2 = f2fma(p1.x, w00, a2); a3 = f2fma(p1.y, w00, a3);
        a4 = f2fma(p2.x, w00, a4); a5 = f2fma(p2.y, w00, a5);
    }
    {   // tap (x0, z1)
        ulonglong2 p0 = PY2[e01], p1 = PY2[e01 + 1], p2 = PY2[e01 + 2];
        a0 = f2fma(p0.x, w01, a0); a1 = f2fma(p0.y, w01, a1);
        a2 = f2fma(p1.x, w01, a2); a3 = f2fma(p1.y, w01, a3);
        a4 = f2fma(p2.x, w01, a4); a5 = f2fma(p2.y, w01, a5);
    }
    {   // tap (x1, z0)
        ulonglong2 p0 = PY2[e10], p1 = PY2[e10 + 1], p2 = PY2[e10 + 2];
        a0 = f2fma(p0.x, w10, a0); a1 = f2fma(p0.y, w10, a1);
        a2 = f2fma(p1.x, w10, a2); a3 = f2fma(p1.y, w10, a3);
        a4 = f2fma(p2.x, w10, a4); a5 = f2fma(p2.y, w10, a5);
    }
    {   // tap (x1, z1)
        ulonglong2 p0 = PY2[e11], p1 = PY2[e11 + 1], p2 = PY2[e11 + 2];
        a0 = f2fma(p0.x, w11, a0); a1 = f2fma(p0.y, w11, a1);
        a2 = f2fma(p1.x, w11, a2); a3 = f2fma(p1.y, w11, a3);
        a4 = f2fma(p2.x, w11, a4); a5 = f2fma(p2.y, w11, a5);
    }

    // coeffs c0..c11 = (a0..a5) unpacked
    const float2 c01 = upk2(a0), c23 = upk2(a1), c45 = upk2(a2);
    const float2 c67 = upk2(a3), c89 = upk2(a4), cab = upk2(a5);

    float* op = out + pix * 3;
    op[0] = c01.x * i0 + c01.y * i1 + c23.x * i2 + c23.y;
    op[1] = c45.x * i0 + c45.y * i1 + c67.x * i2 + c67.y;
    op[2] = c89.x * i0 + c89.y * i1 + cab.x * i2 + cab.y;
}

extern "C" void kernel_launch(void* const* d_in, const int* in_sizes, int n_in,
                              void* d_out, int out_size)
{
    const float* grid  = (const float*)d_in[0];
    const float* guide = (const float*)d_in[1];
    const float* inp   = (const float*)d_in[2];
    float* out = (float*)d_out;

    const int B = in_sizes[1] / (HH * WW);  // 4

    dim3 blk(TPB, 1, 1);
    dim3 grd(WW / TPB, HH, B);              // (2, 1024, 4)
    bsa_kernel<<<grd, blk>>>(grid, guide, inp, out);
}

// round 3
// speedup vs baseline: 1.9807x; 1.2486x over previous
#include <cuda_runtime.h>
#include <cuda_fp16.h>

// BilateralSliceApply on GB300 — Round 3.
// grid (4,16,16,8,12) f32, guide (4,1024,1024), inp/out (4,1024,1024,3).
//
// R2 analysis: kernel is shared-crossbar-bound (L1=73%, 4 taps x 48B = 192B/px).
// R3: store the y-interpolated plane PY in fp16 -> 96 B/px of LDS, 4-tap
// accumulation in half2 (HFMA2), single conversion to f32 at the end.
// Layout PY[xi(10)][z(8)][12 halves = 24B rows]; 8B loads are bank-conflict-free
// for any mix of (xi, xi+1) x z across a warp.

#define GH 16
#define GW 16
#define GD 8
#define HH 1024
#define WW 1024
#define TPB 512              // one 512-px half-row per block
#define NXS 10               // x tap slots (8 cells + 1 halo each side)

__device__ __forceinline__ __half2 u2h(unsigned v) {
    __half2 h; asm("mov.b32 %0, %1;" : "=r"(*(unsigned*)&h) : "r"(v)); return h;
}

__global__ void __launch_bounds__(TPB) bsa_kernel(
    const float* __restrict__ grid,
    const float* __restrict__ guide,
    const float* __restrict__ inp,
    float* __restrict__ out)
{
    // [xi][z][c12] fp16: 10*8*12 halves = 1.875 KB. Indexed as uint2 (8B = 4 halves).
    __shared__ uint2 PY[NXS * GD * 3];

    const int bx  = blockIdx.x;          // 0..1
    const int y   = blockIdx.y;          // 0..1023
    const int b   = blockIdx.z;          // 0..3
    const int tid = threadIdx.x;         // 0..511
    const int x   = bx * TPB + tid;

    // per-pixel global loads issued early
    const size_t pix = (size_t)(b * HH + y) * WW + x;
    const float gdv = __ldg(guide + pix);
    const float i0 = __ldg(inp + pix * 3 + 0);
    const float i1 = __ldg(inp + pix * 3 + 1);
    const float i2 = __ldg(inp + pix * 3 + 2);

    // y taps: uniform over the row.  gy - 0.5 = (2y-63)/128
    const int vy = 2 * y - 63;
    const int fy = vy >> 7;
    const float wy1 = (float)(vy & 127) * (1.0f / 128.0f);
    const float wy0 = 1.0f - wy1;
    const int cy0 = min(max(fy,     0), GH - 1);
    const int cy1 = min(max(fy + 1, 0), GH - 1);

    const int xbase = bx * (TPB / 64) - 1;

    // stage PY = wy0*grid[cy0] + wy1*grid[cy1], rounded to fp16
    if (tid < NXS * GD * 3) {
        const int c4 = tid % 3;            // which float4 of the 12 channels
        const int z  = (tid / 3) & (GD - 1);
        const int xi = tid / (3 * GD);
        const int gx = min(max(xbase + xi, 0), GW - 1);
        const float4* g0 = reinterpret_cast<const float4*>(grid)
            + (size_t)(((b * GH + cy0) * GW + gx) * GD + z) * 3 + c4;
        const float4* g1 = reinterpret_cast<const float4*>(grid)
            + (size_t)(((b * GH + cy1) * GW + gx) * GD + z) * 3 + c4;
        const float4 a = __ldg(g0);
        const float4 bb = __ldg(g1);
        const __half2 h0 = __floats2half2_rn(wy0 * a.x + wy1 * bb.x,
                                             wy0 * a.y + wy1 * bb.y);
        const __half2 h1 = __floats2half2_rn(wy0 * a.z + wy1 * bb.z,
                                             wy0 * a.w + wy1 * bb.w);
        uint2 v;
        v.x = *(const unsigned*)&h0;
        v.y = *(const unsigned*)&h1;
        PY[tid] = v;                       // addr = tid*8 -> conflict-free STS.64
    }
    __syncthreads();

    // x taps:  gx - 0.5 = (2x-63)/128
    const int vx = 2 * x - 63;
    const int fx = vx >> 7;
    const float wx1 = (float)(vx & 127) * (1.0f / 128.0f);
    const float wx0 = 1.0f - wx1;
    const int sx = fx - xbase;             // 0..8

    // z taps from guide
    const float tz = gdv * (float)GD - 0.5f;
    const float fz = floorf(tz);
    const float wz1f = tz - fz;
    const float wz0f = 1.0f - wz1f;
    const int iz = (int)fz;
    const int z0 = min(max(iz,     0), GD - 1);
    const int z1 = min(max(iz + 1, 0), GD - 1);

    // packed tap weights (replicated into both halves)
    const __half2 W00 = __float2half2_rn(wx0 * wz0f);
    const __half2 W01 = __float2half2_rn(wx0 * wz1f);
    const __half2 W10 = __float2half2_rn(wx1 * wz0f);
    const __half2 W11 = __float2half2_rn(wx1 * wz1f);

    // row base indices in uint2 units (3 per 12-channel row)
    const int e00 = (sx * GD + z0) * 3;
    const int e01 = (sx * GD + z1) * 3;
    const int e10 = e00 + GD * 3;
    const int e11 = e01 + GD * 3;

    __half2 a0 = __float2half2_rn(0.f), a1 = a0, a2 = a0,
            a3 = a0, a4 = a0, a5 = a0;

    {   // tap (x0, z0)
        const uint2 q0 = PY[e00], q1 = PY[e00 + 1], q2 = PY[e00 + 2];
        a0 = __hfma2(u2h(q0.x), W00, a0); a1 = __hfma2(u2h(q0.y), W00, a1);
        a2 = __hfma2(u2h(q1.x), W00, a2); a3 = __hfma2(u2h(q1.y), W00, a3);
        a4 = __hfma2(u2h(q2.x), W00, a4); a5 = __hfma2(u2h(q2.y), W00, a5);
    }
    {   // tap (x0, z1)
        const uint2 q0 = PY[e01], q1 = PY[e01 + 1], q2 = PY[e01 + 2];
        a0 = __hfma2(u2h(q0.x), W01, a0); a1 = __hfma2(u2h(q0.y), W01, a1);
        a2 = __hfma2(u2h(q1.x), W01, a2); a3 = __hfma2(u2h(q1.y), W01, a3);
        a4 = __hfma2(u2h(q2.x), W01, a4); a5 = __hfma2(u2h(q2.y), W01, a5);
    }
    {   // tap (x1, z0)
        const uint2 q0 = PY[e10], q1 = PY[e10 + 1], q2 = PY[e10 + 2];
        a0 = __hfma2(u2h(q0.x), W10, a0); a1 = __hfma2(u2h(q0.y), W10, a1);
        a2 = __hfma2(u2h(q1.x), W10, a2); a3 = __hfma2(u2h(q1.y), W10, a3);
        a4 = __hfma2(u2h(q2.x), W10, a4); a5 = __hfma2(u2h(q2.y), W10, a5);
    }
    {   // tap (x1, z1)
        const uint2 q0 = PY[e11], q1 = PY[e11 + 1], q2 = PY[e11 + 2];
        a0 = __hfma2(u2h(q0.x), W11, a0); a1 = __hfma2(u2h(q0.y), W11, a1);
        a2 = __hfma2(u2h(q1.x), W11, a2); a3 = __hfma2(u2h(q1.y), W11, a3);
        a4 = __hfma2(u2h(q2.x), W11, a4); a5 = __hfma2(u2h(q2.y), W11, a5);
    }

    // coeffs c0..c11 (low half = even channel)
    const float c0 = __low2float(a0), c1 = __high2float(a0);
    const float c2 = __low2float(a1), c3 = __high2float(a1);
    const float c4 = __low2float(a2), c5 = __high2float(a2);
    const float c6 = __low2float(a3), c7 = __high2float(a3);
    const float c8 = __low2float(a4), c9 = __high2float(a4);
    const float cA = __low2float(a5), cB = __high2float(a5);

    float* op = out + pix * 3;
    op[0] = c0 * i0 + c1 * i1 + c2 * i2 + c3;
    op[1] = c4 * i0 + c5 * i1 + c6 * i2 + c7;
    op[2] = c8 * i0 + c9 * i1 + cA * i2 + cB;
}

extern "C" void kernel_launch(void* const* d_in, const int* in_sizes, int n_in,
                              void* d_out, int out_size)
{
    const float* grid  = (const float*)d_in[0];
    const float* guide = (const float*)d_in[1];
    const float* inp   = (const float*)d_in[2];
    float* out = (float*)d_out;

    const int B = in_sizes[1] / (HH * WW);  // 4

    dim3 blk(TPB, 1, 1);
    dim3 grd(WW / TPB, HH, B);              // (2, 1024, 4)
    bsa_kernel<<<grd, blk>>>(grid, guide, inp, out);
}

// round 4
// speedup vs baseline: 2.2348x; 1.1283x over previous
#include <cuda_runtime.h>
#include <cuda_fp16.h>

// BilateralSliceApply on GB300 — Round 4.
// grid (4,16,16,8,12) f32, guide (4,1024,1024), inp/out (4,1024,1024,3).
//
// R3 analysis: balanced L1/issue mix; 19/32px L1 wavefronts were scalar
// stride-12B pixel I/O. R4: one block = one full 1024-px row (256 threads,
// 4 px/thread), all pixel I/O as aligned float4 (LDG.128/STG.128).
// The 4 px of a thread share the same x tap cell (fx changes only at
// x = 32 + 64k, never inside a 4-aligned group) -> address bases hoisted.
// PY (y-interpolated grid plane, fp16) covers the whole row: 18 x-slots.

#define GH 16
#define GW 16
#define GD 8
#define HH 1024
#define WW 1024
#define TPB 256
#define NXS 18               // 16 x cells + halo on both sides (xbase = -1)

__device__ __forceinline__ __half2 u2h(unsigned v) {
    __half2 h; asm("mov.b32 %0, %1;" : "=r"(*(unsigned*)&h) : "r"(v)); return h;
}

__global__ void __launch_bounds__(TPB) bsa_kernel(
    const float* __restrict__ grid,
    const float* __restrict__ guide,
    const float* __restrict__ inp,
    float* __restrict__ out)
{
    // [xi(18)][z(8)][c12] fp16 = 3.375 KB, as uint2 (4 halves each)
    __shared__ uint2 PY[NXS * GD * 3];

    const int y   = blockIdx.x;          // 0..1023
    const int b   = blockIdx.y;          // 0..3
    const int tid = threadIdx.x;         // 0..255
    const int x0  = tid * 4;

    // ---- early global loads (overlap with stage) ----
    const size_t rowpix = (size_t)(b * HH + y) * WW;
    const float4 g4 = __ldg(reinterpret_cast<const float4*>(guide + rowpix) + tid);
    const float4* ibase = reinterpret_cast<const float4*>(inp + rowpix * 3);
    const float4 ia = __ldg(ibase + tid * 3 + 0);
    const float4 ib = __ldg(ibase + tid * 3 + 1);
    const float4 ic = __ldg(ibase + tid * 3 + 2);

    // ---- y taps (uniform over the row):  gy - 0.5 = (2y-63)/128 ----
    const int vy = 2 * y - 63;
    const int fy = vy >> 7;
    const float wy1 = (float)(vy & 127) * (1.0f / 128.0f);
    const float wy0 = 1.0f - wy1;
    const int cy0 = min(max(fy,     0), GH - 1);
    const int cy1 = min(max(fy + 1, 0), GH - 1);

    // ---- stage PY = wy0*grid[cy0] + wy1*grid[cy1] (fp16), 432 entries ----
    #pragma unroll
    for (int e = tid; e < NXS * GD * 3; e += TPB) {
        const int c4 = e % 3;
        const int z  = (e / 3) & (GD - 1);
        const int xi = e / (3 * GD);
        const int gx = min(max(xi - 1, 0), GW - 1);
        const float4* g0 = reinterpret_cast<const float4*>(grid)
            + (size_t)(((b * GH + cy0) * GW + gx) * GD + z) * 3 + c4;
        const float4* g1 = reinterpret_cast<const float4*>(grid)
            + (size_t)(((b * GH + cy1) * GW + gx) * GD + z) * 3 + c4;
        const float4 a  = __ldg(g0);
        const float4 bb = __ldg(g1);
        const __half2 h0 = __floats2half2_rn(wy0 * a.x + wy1 * bb.x,
                                             wy0 * a.y + wy1 * bb.y);
        const __half2 h1 = __floats2half2_rn(wy0 * a.z + wy1 * bb.z,
                                             wy0 * a.w + wy1 * bb.w);
        uint2 v;
        v.x = *(const unsigned*)&h0;
        v.y = *(const unsigned*)&h1;
        PY[e] = v;
    }
    __syncthreads();

    // ---- x taps: fx/sx uniform over the thread's 4 pixels ----
    const int vx = 2 * x0 - 63;
    const int fx = vx >> 7;                        // unclamped floor
    const float wx1base = (float)(vx & 127) * (1.0f / 128.0f);
    const int sx = fx + 1;                         // xbase = -1
    const int ebase0 = sx * (GD * 3);
    const int ebase1 = ebase0 + GD * 3;

    const float gin[4] = {g4.x, g4.y, g4.z, g4.w};
    const float fin[12] = {ia.x, ia.y, ia.z, ia.w, ib.x, ib.y,
                           ib.z, ib.w, ic.x, ic.y, ic.z, ic.w};
    float o[12];

    #pragma unroll
    for (int p = 0; p < 4; p++) {
        const float wx1 = wx1base + (float)p * (2.0f / 128.0f);
        const float wx0 = 1.0f - wx1;

        // z taps from guide
        const float tz = fmaf(gin[p], (float)GD, -0.5f);
        const float fz = floorf(tz);
        const float wz1 = tz - fz;
        const float wz0 = 1.0f - wz1;
        const int iz = (int)fz;
        const int z0 = min(max(iz,     0), GD - 1);
        const int z1 = min(max(iz + 1, 0), GD - 1);

        const __half2 W00 = __float2half2_rn(wx0 * wz0);
        const __half2 W01 = __float2half2_rn(wx0 * wz1);
        const __half2 W10 = __float2half2_rn(wx1 * wz0);
        const __half2 W11 = __float2half2_rn(wx1 * wz1);

        const int e00 = ebase0 + z0 * 3;
        const int e01 = ebase0 + z1 * 3;
        const int e10 = ebase1 + z0 * 3;
        const int e11 = ebase1 + z1 * 3;

        __half2 a0 = __float2half2_rn(0.f), a1 = a0, a2 = a0,
                a3 = a0, a4 = a0, a5 = a0;
        {
            const uint2 q0 = PY[e00], q1 = PY[e00 + 1], q2 = PY[e00 + 2];
            a0 = __hfma2(u2h(q0.x), W00, a0); a1 = __hfma2(u2h(q0.y), W00, a1);
            a2 = __hfma2(u2h(q1.x), W00, a2); a3 = __hfma2(u2h(q1.y), W00, a3);
            a4 = __hfma2(u2h(q2.x), W00, a4); a5 = __hfma2(u2h(q2.y), W00, a5);
        }
        {
            const uint2 q0 = PY[e01], q1 = PY[e01 + 1], q2 = PY[e01 + 2];
            a0 = __hfma2(u2h(q0.x), W01, a0); a1 = __hfma2(u2h(q0.y), W01, a1);
            a2 = __hfma2(u2h(q1.x), W01, a2); a3 = __hfma2(u2h(q1.y), W01, a3);
            a4 = __hfma2(u2h(q2.x), W01, a4); a5 = __hfma2(u2h(q2.y), W01, a5);
        }
        {
            const uint2 q0 = PY[e10], q1 = PY[e10 + 1], q2 = PY[e10 + 2];
            a0 = __hfma2(u2h(q0.x), W10, a0); a1 = __hfma2(u2h(q0.y), W10, a1);
            a2 = __hfma2(u2h(q1.x), W10, a2); a3 = __hfma2(u2h(q1.y), W10, a3);
            a4 = __hfma2(u2h(q2.x), W10, a4); a5 = __hfma2(u2h(q2.y), W10, a5);
        }
        {
            const uint2 q0 = PY[e11], q1 = PY[e11 + 1], q2 = PY[e11 + 2];
            a0 = __hfma2(u2h(q0.x), W11, a0); a1 = __hfma2(u2h(q0.y), W11, a1);
            a2 = __hfma2(u2h(q1.x), W11, a2); a3 = __hfma2(u2h(q1.y), W11, a3);
            a4 = __hfma2(u2h(q2.x), W11, a4); a5 = __hfma2(u2h(q2.y), W11, a5);
        }

        const float c0 = __low2float(a0), c1 = __high2float(a0);
        const float c2 = __low2float(a1), c3 = __high2float(a1);
        const float c4 = __low2float(a2), c5 = __high2float(a2);
        const float c6 = __low2float(a3), c7 = __high2float(a3);
        const float c8 = __low2float(a4), c9 = __high2float(a4);
        const float cA = __low2float(a5), cB = __high2float(a5);

        const float i0 = fin[3 * p], i1 = fin[3 * p + 1], i2 = fin[3 * p + 2];
        o[3 * p + 0] = c0 * i0 + c1 * i1 + c2 * i2 + c3;
        o[3 * p + 1] = c4 * i0 + c5 * i1 + c6 * i2 + c7;
        o[3 * p + 2] = c8 * i0 + c9 * i1 + cA * i2 + cB;
    }

    // ---- vectorized store: 3 STG.128 ----
    float4* obase = reinterpret_cast<float4*>(out + rowpix * 3);
    obase[tid * 3 + 0] = make_float4(o[0], o[1], o[2],  o[3]);
    obase[tid * 3 + 1] = make_float4(o[4], o[5], o[6],  o[7]);
    obase[tid * 3 + 2] = make_float4(o[8], o[9], o[10], o[11]);
}

extern "C" void kernel_launch(void* const* d_in, const int* in_sizes, int n_in,
                              void* d_out, int out_size)
{
    const float* grid  = (const float*)d_in[0];
    const float* guide = (const float*)d_in[1];
    const float* inp   = (const float*)d_in[2];
    float* out = (float*)d_out;

    const int B = in_sizes[1] / (HH * WW);  // 4

    dim3 blk(TPB, 1, 1);
    dim3 grd(HH, B, 1);                     // one block per image row
    bsa_kernel<<<grd, blk>>>(grid, guide, inp, out);
}